// round 1
// baseline (speedup 1.0000x reference)
#include <cuda_runtime.h>
#include <cstdint>

#define BATCH 32
#define GRID  64
#define NCH   255
#define NANCH 3
#define NDIM  85            // 5 + 80 classes
#define NDET  (GRID*GRID*NANCH)   // 12288
#define NSORT 16384
#define TOPK  1024
#define PLANE (GRID*GRID)   // 4096
#define STRIDE_OUT 8.0f     // 512 / 64
#define CNF 0.5f
#define IOU_T 0.4f
#define CLS_OFF 10000.0f

// -------- static scratch (no allocations allowed) --------
__device__ float              g_det[BATCH * NDET * 7];        // ~11 MB
__device__ unsigned long long g_keys[BATCH * NDET];           // ~3 MB
__device__ int                g_topidx[BATCH * TOPK];

// ============================================================
// Kernel 1: decode. blockIdx.x = j (axis-1), blockIdx.y = b, thread = i (axis-2, contiguous)
// t[n,d] = img[a*85+d, j, i], n = (i*64 + j)*3 + a
// ============================================================
__global__ void decode_kernel(const float* __restrict__ in)
{
    const int i = threadIdx.x;        // 0..63, contiguous input dim
    const int j = blockIdx.x;         // 0..63
    const int b = blockIdx.y;         // 0..31

    const float* img = in + (size_t)b * NCH * PLANE + j * GRID + i;

    #pragma unroll
    for (int a = 0; a < NANCH; a++) {
        const float* p = img + (size_t)(a * NDIM) * PLANE;
        float tx = p[0];
        float ty = p[PLANE];
        float tw = p[2 * PLANE];
        float th = p[3 * PLANE];
        float tc = p[4 * PLANE];

        float best = p[5 * PLANE];
        int   bi   = 0;
        #pragma unroll 4
        for (int d = 6; d < NDIM; d++) {
            float v = p[(size_t)d * PLANE];
            if (v > best) { best = v; bi = d - 5; }
        }

        float conf = 1.0f / (1.0f + expf(-tc));

        int n = (i * GRID + j) * NANCH + a;
        float xo = (float)((n >> 6) & 63);
        float yo = (float)(n & 63);
        float cx = tx + xo;
        float cy = ty + yo;
        float hw = tw * 0.5f;
        float hh = th * 0.5f;

        float* dr = g_det + ((size_t)b * NDET + n) * 7;
        dr[0] = cx - hw;
        dr[1] = cy - hh;
        dr[2] = cx + hw;
        dr[3] = cy + hh;
        dr[4] = conf;
        dr[5] = best;
        dr[6] = (float)bi;

        // sort key: (conf_bits if conf>0.5 else 0) desc, then index asc.
        unsigned cb = (conf > CNF) ? __float_as_uint(conf) : 0u;
        g_keys[(size_t)b * NDET + n] =
            ((unsigned long long)cb << 32) | (unsigned long long)(0xFFFFFFFFu - (unsigned)n);
    }
}

// ============================================================
// Kernel 2: per-image bitonic sort (descending) of 16384 keys in smem.
// ============================================================
__global__ void sort_kernel()
{
    extern __shared__ unsigned long long skey[];   // 16384 * 8 = 128 KB
    const int b   = blockIdx.x;
    const int tid = threadIdx.x;

    for (int idx = tid; idx < NSORT; idx += blockDim.x)
        skey[idx] = (idx < NDET) ? g_keys[(size_t)b * NDET + idx] : 0ULL;
    __syncthreads();

    for (int k = 2; k <= NSORT; k <<= 1) {
        for (int jj = k >> 1; jj > 0; jj >>= 1) {
            for (int idx = tid; idx < NSORT; idx += blockDim.x) {
                int ixj = idx ^ jj;
                if (ixj > idx) {
                    bool desc = ((idx & k) == 0);
                    unsigned long long A = skey[idx];
                    unsigned long long C = skey[ixj];
                    if (desc ? (A < C) : (A > C)) { skey[idx] = C; skey[ixj] = A; }
                }
            }
            __syncthreads();
        }
    }

    if (tid < TOPK) {
        unsigned low = (unsigned)(skey[tid] & 0xFFFFFFFFull);
        g_topidx[b * TOPK + tid] = (int)(0xFFFFFFFFu - low);
    }
}

// ============================================================
// Kernel 3: NMS per image. 1024 threads. smem:
//   sx1,sy1,sx2,sy2,sarea : 5 * 4096
//   valid(int), keep(int) : 2 * 4096
//   mask: 1024 rows * 33 words (padded stride to avoid bank conflicts)
// ============================================================
#define NMS_SMEM (7*4096 + 1024*33*4)

__global__ void nms_kernel(float* __restrict__ out)
{
    extern __shared__ char smem[];
    float*    sx1   = (float*)(smem);
    float*    sy1   = (float*)(smem + 4096);
    float*    sx2   = (float*)(smem + 8192);
    float*    sy2   = (float*)(smem + 12288);
    float*    sarea = (float*)(smem + 16384);
    int*      valid = (int*)  (smem + 20480);
    int*      keep  = (int*)  (smem + 24576);
    unsigned* mask  = (unsigned*)(smem + 28672);

    const int b = blockIdx.x;
    const int i = threadIdx.x;

    // gather candidate row
    int idx = g_topidx[b * TOPK + i];
    const float* dr = g_det + ((size_t)b * NDET + idx) * 7;
    float r0 = dr[0], r1 = dr[1], r2 = dr[2], r3 = dr[3];
    float r4 = dr[4], r5 = dr[5], r6 = dr[6];

    valid[i] = (r4 > CNF) ? 1 : 0;

    float off = r6 * CLS_OFF;
    float ax1 = r0 + off, ay1 = r1 + off, ax2 = r2 + off, ay2 = r3 + off;
    sx1[i] = ax1; sy1[i] = ay1; sx2[i] = ax2; sy2[i] = ay2;
    float areaA = (ax2 - ax1) * (ay2 - ay1);
    sarea[i] = areaA;
    __syncthreads();

    // build suppression mask row i (only bits j > i)
    const int w0 = i >> 5;
    for (int w = 0; w < w0; w++) mask[i * 33 + w] = 0u;
    for (int w = w0; w < 32; w++) {
        unsigned cur = 0u;
        #pragma unroll 8
        for (int bit = 0; bit < 32; bit++) {
            int jdx = (w << 5) + bit;
            if (jdx > i) {
                float lx = fmaxf(ax1, sx1[jdx]);
                float ly = fmaxf(ay1, sy1[jdx]);
                float rx = fminf(ax2, sx2[jdx]);
                float ry = fminf(ay2, sy2[jdx]);
                float ww = fmaxf(rx - lx, 0.0f);
                float hh = fmaxf(ry - ly, 0.0f);
                float inter = ww * hh;
                float iou = inter / (areaA + sarea[jdx] - inter + 1e-9f);
                if (iou > IOU_T) cur |= (1u << bit);
            }
        }
        mask[i * 33 + w] = cur;
    }
    __syncthreads();

    // warp-serial greedy scan: lane owns one word of the suppressed vector
    if (i < 32) {
        unsigned my_sup = 0u;
        for (int r = 0; r < TOPK; r++) {
            unsigned sw = __shfl_sync(0xFFFFFFFFu, my_sup, r >> 5);
            bool kept = !((sw >> (r & 31)) & 1u) && (valid[r] != 0);
            if (kept) my_sup |= mask[r * 33 + i];
            if (i == 0) keep[r] = kept ? 1 : 0;
        }
    }
    __syncthreads();

    // write outputs: dets then keep flags
    bool kp = (keep[i] != 0);
    float* o = out + ((size_t)b * TOPK + i) * 7;
    if (kp) {
        o[0] = STRIDE_OUT * r0; o[1] = STRIDE_OUT * r1;
        o[2] = STRIDE_OUT * r2; o[3] = STRIDE_OUT * r3;
        o[4] = STRIDE_OUT * r4; o[5] = STRIDE_OUT * r5;
        o[6] = STRIDE_OUT * r6;
    } else {
        o[0] = 0.f; o[1] = 0.f; o[2] = 0.f; o[3] = 0.f;
        o[4] = 0.f; o[5] = 0.f; o[6] = 0.f;
    }
    out[(size_t)BATCH * TOPK * 7 + (size_t)b * TOPK + i] = kp ? 1.0f : 0.0f;
}

// ============================================================
extern "C" void kernel_launch(void* const* d_in, const int* in_sizes, int n_in,
                              void* d_out, int out_size)
{
    const float* in = (const float*)d_in[0];
    float* out = (float*)d_out;

    decode_kernel<<<dim3(GRID, BATCH), GRID>>>(in);

    cudaFuncSetAttribute(sort_kernel, cudaFuncAttributeMaxDynamicSharedMemorySize,
                         NSORT * sizeof(unsigned long long));
    sort_kernel<<<BATCH, 1024, NSORT * sizeof(unsigned long long)>>>();

    cudaFuncSetAttribute(nms_kernel, cudaFuncAttributeMaxDynamicSharedMemorySize, NMS_SMEM);
    nms_kernel<<<BATCH, 1024, NMS_SMEM>>>(out);
}

// round 4
// speedup vs baseline: 2.7024x; 2.7024x over previous
#include <cuda_runtime.h>
#include <cstdint>
#include <float.h>

#define BATCH 32
#define GRID  64
#define NCH   255
#define NANCH 3
#define NDIM  85
#define NDET  (GRID*GRID*NANCH)   // 12288
#define TOPK  1024
#define PLANE (GRID*GRID)         // 4096
#define STRIDE_OUT 8.0f
#define CNF 0.5f
#define IOU_T 0.4f
#define CLS_OFF 10000.0f
#define KEYS_PER_T 12             // 12288 / 1024

// -------- static scratch --------
__device__ float4             g_boxes[BATCH * NDET];      // x1,y1,x2,y2
__device__ float4             g_extra[BATCH * NDET];      // conf, maxval, cls, pad
__device__ unsigned long long g_keys [BATCH * NDET];
__device__ int                g_topidx[BATCH * TOPK];
__device__ unsigned           g_mask[BATCH * TOPK * 32];  // 4 MB

// ============================================================
// Kernel 1: decode.  block = (64 i, 4 j), grid = (16 j-groups, 32 b)
// ============================================================
__global__ void __launch_bounds__(256) decode_kernel(const float* __restrict__ in)
{
    const int i = threadIdx.x;                       // 0..63 contiguous input dim
    const int j = blockIdx.x * 4 + threadIdx.y;      // 0..63
    const int b = blockIdx.y;

    const float* img = in + (size_t)b * NCH * PLANE + j * GRID + i;
    const float* pa[NANCH];
    #pragma unroll
    for (int a = 0; a < NANCH; a++) pa[a] = img + (size_t)(a * NDIM) * PLANE;

    float best[NANCH];
    int   bi[NANCH];
    #pragma unroll
    for (int a = 0; a < NANCH; a++) { best[a] = -FLT_MAX; bi[a] = 0; }

    // class max: batches of 8 loads per anchor in flight
    #pragma unroll 2
    for (int c0 = 0; c0 < 80; c0 += 8) {
        #pragma unroll
        for (int a = 0; a < NANCH; a++) {
            float v[8];
            #pragma unroll
            for (int k = 0; k < 8; k++)
                v[k] = pa[a][(size_t)(5 + c0 + k) * PLANE];
            #pragma unroll
            for (int k = 0; k < 8; k++)
                if (v[k] > best[a]) { best[a] = v[k]; bi[a] = c0 + k; }
        }
    }

    #pragma unroll
    for (int a = 0; a < NANCH; a++) {
        const float* p = pa[a];
        float tx = p[0];
        float ty = p[PLANE];
        float tw = p[2 * PLANE];
        float th = p[3 * PLANE];
        float tc = p[4 * PLANE];

        float conf = 1.0f / (1.0f + expf(-tc));

        int n = (i * GRID + j) * NANCH + a;
        float xo = (float)((n >> 6) & 63);
        float yo = (float)(n & 63);
        float cx = tx + xo;
        float cy = ty + yo;
        float hw = tw * 0.5f;
        float hh = th * 0.5f;

        size_t row = (size_t)b * NDET + n;
        g_boxes[row] = make_float4(cx - hw, cy - hh, cx + hw, cy + hh);
        g_extra[row] = make_float4(conf, best[a], (float)bi[a], 0.0f);

        unsigned cb = (conf > CNF) ? __float_as_uint(conf) : 0u;
        g_keys[row] = ((unsigned long long)cb << 32)
                    | (unsigned long long)(0xFFFFFFFFu - (unsigned)n);
    }
}

// ============================================================
// Kernel 2: top-k select per image. 1 block x 1024 threads.
// Histogram over conf-mantissa buckets, gather bucket >= T, sort 2048.
// ============================================================
__global__ void __launch_bounds__(1024) select_kernel()
{
    __shared__ int hist[257];
    __shared__ unsigned long long buf[4096];
    __shared__ int scanbuf[1024];
    __shared__ int s_T, s_m, s_cnt;

    const int b = blockIdx.x;
    const int t = threadIdx.x;

    for (int q = t; q < 257; q += 1024) hist[q] = 0;
    __syncthreads();

    // cache keys in regs (thread t owns contiguous n = t*12 .. t*12+11)
    unsigned long long kreg[KEYS_PER_T];
    int bkt[KEYS_PER_T];
    #pragma unroll
    for (int e = 0; e < KEYS_PER_T; e++) {
        int n = t * KEYS_PER_T + e;
        unsigned long long k = g_keys[(size_t)b * NDET + n];
        kreg[e] = k;
        unsigned hi = (unsigned)(k >> 32);
        // valid conf bits lie in (0x3F000000, 0x3F800000]; map monotonically to 1..256
        int bv;
        if (hi == 0u) bv = 0;
        else {
            unsigned d = (hi - 0x3F000000u) >> 15;
            bv = 1 + (int)((d > 255u) ? 255u : d);
        }
        bkt[e] = bv;
        atomicAdd(&hist[bv], 1);
    }
    __syncthreads();

    if (t == 0) {
        int c = 0, T = 0, st = 0;
        for (int bk = 256; bk >= 0; bk--) {
            st = c;
            c += hist[bk];
            if (c >= TOPK) { T = bk; break; }
        }
        s_T = T;
        int m = st + hist[T];
        if (m > 4096) m = 4096;        // adversarial-data guard
        s_m = m;
        s_cnt = 0;
    }
    __syncthreads();

    const int T = s_T;

    if (T >= 1) {
        #pragma unroll
        for (int e = 0; e < KEYS_PER_T; e++) {
            if (bkt[e] >= T) {
                int pos = atomicAdd(&s_cnt, 1);
                if (pos < 4096) buf[pos] = kreg[e];
            }
        }
    } else {
        // fewer than TOPK valid: take all valid, then smallest-index invalids.
        #pragma unroll
        for (int e = 0; e < KEYS_PER_T; e++) {
            if (bkt[e] >= 1) {
                int pos = atomicAdd(&s_cnt, 1);
                if (pos < 4096) buf[pos] = kreg[e];
            }
        }
        __syncthreads();
        int nvalid = s_cnt;
        int need = TOPK - nvalid;
        int local = 0;
        #pragma unroll
        for (int e = 0; e < KEYS_PER_T; e++) if (bkt[e] == 0) local++;
        scanbuf[t] = local;
        __syncthreads();
        for (int off = 1; off < 1024; off <<= 1) {
            int v = (t >= off) ? scanbuf[t - off] : 0;
            __syncthreads();
            scanbuf[t] += v;
            __syncthreads();
        }
        int r = scanbuf[t] - local;   // exclusive prefix of invalid count
        #pragma unroll
        for (int e = 0; e < KEYS_PER_T; e++) {
            if (bkt[e] == 0) {
                if (r < need) buf[nvalid + r] = kreg[e];
                r++;
            }
        }
        if (t == 0) s_m = TOPK;
    }
    __syncthreads();

    const int m = s_m;
    const int S = (m <= 2048) ? 2048 : 4096;
    for (int idx = t; idx < S; idx += 1024)
        if (idx >= m) buf[idx] = 0ULL;
    __syncthreads();

    // bitonic sort descending (key = conf desc, index asc on ties/invalid)
    for (int k = 2; k <= S; k <<= 1) {
        for (int jj = k >> 1; jj > 0; jj >>= 1) {
            for (int idx = t; idx < S; idx += 1024) {
                int ixj = idx ^ jj;
                if (ixj > idx) {
                    bool desc = ((idx & k) == 0);
                    unsigned long long A = buf[idx];
                    unsigned long long C = buf[ixj];
                    if (desc ? (A < C) : (A > C)) { buf[idx] = C; buf[ixj] = A; }
                }
            }
            __syncthreads();
        }
    }

    if (t < TOPK) {
        unsigned low = (unsigned)(buf[t] & 0xFFFFFFFFull);
        g_topidx[b * TOPK + t] = (int)(0xFFFFFFFFu - low);
    }
}

// ============================================================
// Kernel 3: IOU mask build. grid (4 chunks, 32 b) x 1024 threads.
// Block c handles rows r with r % 4 == c. 4 threads/row, 8 words each.
// ============================================================
__global__ void __launch_bounds__(1024) mask_kernel()
{
    __shared__ float sx1[TOPK], sy1[TOPK], sx2[TOPK], sy2[TOPK], sar[TOPK];

    const int c = blockIdx.x;
    const int b = blockIdx.y;
    const int t = threadIdx.x;

    // gather all candidate boxes (class-shifted)
    {
        int idx = g_topidx[b * TOPK + t];
        float4 bx = g_boxes[(size_t)b * NDET + idx];
        float4 ex = g_extra[(size_t)b * NDET + idx];
        float off = ex.z * CLS_OFF;
        float ax1 = bx.x + off, ay1 = bx.y + off;
        float ax2 = bx.z + off, ay2 = bx.w + off;
        sx1[t] = ax1; sy1[t] = ay1; sx2[t] = ax2; sy2[t] = ay2;
        sar[t] = (ax2 - ax1) * (ay2 - ay1);
    }
    __syncthreads();

    const int row = ((t >> 2) << 2) + c;   // rows == c (mod 4)
    const int wg  = t & 3;                 // words wg*8 .. wg*8+7

    float ax1 = sx1[row], ay1 = sy1[row];
    float ax2 = sx2[row], ay2 = sy2[row];
    float areaA = sar[row];

    unsigned words[8];
    #pragma unroll
    for (int k = 0; k < 8; k++) {
        int w = wg * 8 + k;
        unsigned cur = 0u;
        if ((w + 1) * 32 > row + 1) {          // word contains some j > row
            #pragma unroll 8
            for (int bit = 0; bit < 32; bit++) {
                int j = (w << 5) + bit;
                if (j > row) {
                    float lx = fmaxf(ax1, sx1[j]);
                    float ly = fmaxf(ay1, sy1[j]);
                    float rx = fminf(ax2, sx2[j]);
                    float ry = fminf(ay2, sy2[j]);
                    float ww = fmaxf(rx - lx, 0.0f);
                    float hh = fmaxf(ry - ly, 0.0f);
                    float inter = ww * hh;
                    float iou = inter / (areaA + sar[j] - inter + 1e-9f);
                    if (iou > IOU_T) cur |= (1u << bit);
                }
            }
        }
        words[k] = cur;
    }

    unsigned* gm = &g_mask[((size_t)b * TOPK + row) * 32 + wg * 8];
    ((uint4*)gm)[0] = make_uint4(words[0], words[1], words[2], words[3]);
    ((uint4*)gm)[1] = make_uint4(words[4], words[5], words[6], words[7]);
}

// ============================================================
// Kernel 4: greedy scan + output. 32 blocks x 1024 threads.
// smem: mask copy 128KB + valid 4KB + keep 4KB (dynamic).
// ============================================================
#define FINISH_SMEM (TOPK*32*4 + TOPK*4*2)

__global__ void __launch_bounds__(1024) finish_kernel(float* __restrict__ out)
{
    extern __shared__ char smemraw[];
    unsigned* smask = (unsigned*)smemraw;             // 1024*32 words
    int* valid = (int*)(smemraw + TOPK * 32 * 4);
    int* keepA = valid + TOPK;

    const int b = blockIdx.x;
    const int t = threadIdx.x;

    // gather candidate row (for valid + output)
    int idx = g_topidx[b * TOPK + t];
    float4 bx = g_boxes[(size_t)b * NDET + idx];
    float4 ex = g_extra[(size_t)b * NDET + idx];
    valid[t] = (ex.x > CNF) ? 1 : 0;

    // copy mask into smem, coalesced uint4
    {
        const uint4* gm = (const uint4*)&g_mask[(size_t)b * TOPK * 32];
        uint4* sm = (uint4*)smask;
        #pragma unroll
        for (int q = 0; q < 8; q++)
            sm[t + q * 1024] = gm[t + q * 1024];
    }
    __syncthreads();

    // warp-serial greedy scan: lane i owns suppressed word i
    if (t < 32) {
        unsigned my_sup = 0u;
        for (int r = 0; r < TOPK; r++) {
            unsigned sw = __shfl_sync(0xFFFFFFFFu, my_sup, r >> 5);
            bool kept = !((sw >> (r & 31)) & 1u) && (valid[r] != 0);
            if (kept) my_sup |= smask[r * 32 + t];
            if (t == 0) keepA[r] = kept ? 1 : 0;
        }
    }
    __syncthreads();

    bool kp = (keepA[t] != 0);
    float* o = out + ((size_t)b * TOPK + t) * 7;
    if (kp) {
        o[0] = STRIDE_OUT * bx.x; o[1] = STRIDE_OUT * bx.y;
        o[2] = STRIDE_OUT * bx.z; o[3] = STRIDE_OUT * bx.w;
        o[4] = STRIDE_OUT * ex.x; o[5] = STRIDE_OUT * ex.y;
        o[6] = STRIDE_OUT * ex.z;
    } else {
        o[0] = 0.f; o[1] = 0.f; o[2] = 0.f; o[3] = 0.f;
        o[4] = 0.f; o[5] = 0.f; o[6] = 0.f;
    }
    out[(size_t)BATCH * TOPK * 7 + (size_t)b * TOPK + t] = kp ? 1.0f : 0.0f;
}

// ============================================================
extern "C" void kernel_launch(void* const* d_in, const int* in_sizes, int n_in,
                              void* d_out, int out_size)
{
    const float* in = (const float*)d_in[0];
    float* out = (float*)d_out;

    decode_kernel<<<dim3(16, BATCH), dim3(64, 4)>>>(in);
    select_kernel<<<BATCH, 1024>>>();
    mask_kernel<<<dim3(4, BATCH), 1024>>>();

    cudaFuncSetAttribute(finish_kernel, cudaFuncAttributeMaxDynamicSharedMemorySize,
                         FINISH_SMEM);
    finish_kernel<<<BATCH, 1024, FINISH_SMEM>>>(out);
}

// round 5
// speedup vs baseline: 3.5164x; 1.3012x over previous
#include <cuda_runtime.h>
#include <cstdint>
#include <float.h>

#define BATCH 32
#define GRID  64
#define NCH   255
#define NANCH 3
#define NDIM  85
#define NDET  (GRID*GRID*NANCH)   // 12288
#define TOPK  1024
#define PLANE (GRID*GRID)         // 4096
#define STRIDE_OUT 8.0f
#define CNF 0.5f
#define IOU_T 0.4f
#define CLS_OFF 10000.0f
#define KEYS_PER_T 12             // 12288 / 1024

// -------- static scratch --------
__device__ float4             g_boxes[BATCH * NDET];      // x1,y1,x2,y2
__device__ float4             g_extra[BATCH * NDET];      // conf, maxval, cls, pad
__device__ unsigned long long g_keys [BATCH * NDET];
__device__ int                g_topidx[BATCH * TOPK];
__device__ unsigned           g_mask[BATCH * TOPK * 32];  // 4 MB

// ============================================================
// Kernel 1: decode.  block = (64 i, 4 j), grid = (16 j-groups, 32 b)
// ============================================================
__global__ void __launch_bounds__(256) decode_kernel(const float* __restrict__ in)
{
    const int i = threadIdx.x;                       // 0..63 contiguous input dim
    const int j = blockIdx.x * 4 + threadIdx.y;      // 0..63
    const int b = blockIdx.y;

    const float* img = in + (size_t)b * NCH * PLANE + j * GRID + i;
    const float* pa[NANCH];
    #pragma unroll
    for (int a = 0; a < NANCH; a++) pa[a] = img + (size_t)(a * NDIM) * PLANE;

    float best[NANCH];
    int   bi[NANCH];
    #pragma unroll
    for (int a = 0; a < NANCH; a++) { best[a] = -FLT_MAX; bi[a] = 0; }

    // class max: batches of 8 loads per anchor in flight
    #pragma unroll 2
    for (int c0 = 0; c0 < 80; c0 += 8) {
        #pragma unroll
        for (int a = 0; a < NANCH; a++) {
            float v[8];
            #pragma unroll
            for (int k = 0; k < 8; k++)
                v[k] = pa[a][(size_t)(5 + c0 + k) * PLANE];
            #pragma unroll
            for (int k = 0; k < 8; k++)
                if (v[k] > best[a]) { best[a] = v[k]; bi[a] = c0 + k; }
        }
    }

    #pragma unroll
    for (int a = 0; a < NANCH; a++) {
        const float* p = pa[a];
        float tx = p[0];
        float ty = p[PLANE];
        float tw = p[2 * PLANE];
        float th = p[3 * PLANE];
        float tc = p[4 * PLANE];

        float conf = 1.0f / (1.0f + expf(-tc));

        int n = (i * GRID + j) * NANCH + a;
        float xo = (float)((n >> 6) & 63);
        float yo = (float)(n & 63);
        float cx = tx + xo;
        float cy = ty + yo;
        float hw = tw * 0.5f;
        float hh = th * 0.5f;

        size_t row = (size_t)b * NDET + n;
        g_boxes[row] = make_float4(cx - hw, cy - hh, cx + hw, cy + hh);
        g_extra[row] = make_float4(conf, best[a], (float)bi[a], 0.0f);

        unsigned cb = (conf > CNF) ? __float_as_uint(conf) : 0u;
        g_keys[row] = ((unsigned long long)cb << 32)
                    | (unsigned long long)(0xFFFFFFFFu - (unsigned)n);
    }
}

// ============================================================
// Kernel 2: top-k select per image. 1 block x 1024 threads.
// ============================================================
__global__ void __launch_bounds__(1024) select_kernel()
{
    __shared__ int hist[257];
    __shared__ unsigned long long buf[4096];
    __shared__ int scanbuf[1024];
    __shared__ int s_T, s_m, s_cnt;

    const int b = blockIdx.x;
    const int t = threadIdx.x;
    const int lane = t & 31;

    for (int q = t; q < 257; q += 1024) hist[q] = 0;
    __syncthreads();

    // cache keys in regs (thread t owns contiguous n = t*12 .. t*12+11)
    unsigned long long kreg[KEYS_PER_T];
    int bkt[KEYS_PER_T];
    #pragma unroll
    for (int e = 0; e < KEYS_PER_T; e++) {
        int n = t * KEYS_PER_T + e;
        unsigned long long k = g_keys[(size_t)b * NDET + n];
        kreg[e] = k;
        unsigned hi = (unsigned)(k >> 32);
        int bv;
        if (hi == 0u) bv = 0;
        else {
            unsigned d = (hi - 0x3F000000u) >> 15;
            bv = 1 + (int)((d > 255u) ? 255u : d);
        }
        bkt[e] = bv;
        // warp-aggregate the heavily contended bucket 0; individual adds otherwise
        unsigned zmask = __ballot_sync(0xFFFFFFFFu, bv == 0);
        if (bv == 0) {
            if (lane == (int)(__ffs(zmask) - 1))
                atomicAdd(&hist[0], __popc(zmask));
        } else {
            atomicAdd(&hist[bv], 1);
        }
    }
    __syncthreads();

    if (t == 0) {
        int c = 0, T = 0, st = 0;
        for (int bk = 256; bk >= 0; bk--) {
            st = c;
            c += hist[bk];
            if (c >= TOPK) { T = bk; break; }
        }
        s_T = T;
        int m = st + hist[T];
        if (m > 4096) m = 4096;        // adversarial-data guard
        s_m = m;
        s_cnt = 0;
    }
    __syncthreads();

    const int T = s_T;

    if (T >= 1) {
        #pragma unroll
        for (int e = 0; e < KEYS_PER_T; e++) {
            if (bkt[e] >= T) {
                int pos = atomicAdd(&s_cnt, 1);
                if (pos < 4096) buf[pos] = kreg[e];
            }
        }
    } else {
        // fewer than TOPK valid: take all valid, then smallest-index invalids.
        #pragma unroll
        for (int e = 0; e < KEYS_PER_T; e++) {
            if (bkt[e] >= 1) {
                int pos = atomicAdd(&s_cnt, 1);
                if (pos < 4096) buf[pos] = kreg[e];
            }
        }
        __syncthreads();
        int nvalid = s_cnt;
        int need = TOPK - nvalid;
        int local = 0;
        #pragma unroll
        for (int e = 0; e < KEYS_PER_T; e++) if (bkt[e] == 0) local++;
        scanbuf[t] = local;
        __syncthreads();
        for (int off = 1; off < 1024; off <<= 1) {
            int v = (t >= off) ? scanbuf[t - off] : 0;
            __syncthreads();
            scanbuf[t] += v;
            __syncthreads();
        }
        int r = scanbuf[t] - local;   // exclusive prefix of invalid count
        #pragma unroll
        for (int e = 0; e < KEYS_PER_T; e++) {
            if (bkt[e] == 0) {
                if (r < need) buf[nvalid + r] = kreg[e];
                r++;
            }
        }
        if (t == 0) s_m = TOPK;
    }
    __syncthreads();

    const int m = s_m;
    const int S = (m <= 2048) ? 2048 : 4096;
    for (int idx = t; idx < S; idx += 1024)
        if (idx >= m) buf[idx] = 0ULL;
    __syncthreads();

    // bitonic sort descending (key = conf desc, index asc on ties/invalid)
    for (int k = 2; k <= S; k <<= 1) {
        for (int jj = k >> 1; jj > 0; jj >>= 1) {
            for (int idx = t; idx < S; idx += 1024) {
                int ixj = idx ^ jj;
                if (ixj > idx) {
                    bool desc = ((idx & k) == 0);
                    unsigned long long A = buf[idx];
                    unsigned long long C = buf[ixj];
                    if (desc ? (A < C) : (A > C)) { buf[idx] = C; buf[ixj] = A; }
                }
            }
            __syncthreads();
        }
    }

    if (t < TOPK) {
        unsigned low = (unsigned)(buf[t] & 0xFFFFFFFFull);
        g_topidx[b * TOPK + t] = (int)(0xFFFFFFFFu - low);
    }
}

// ============================================================
// Kernel 3: IOU mask build. grid (4 chunks, 32 b) x 1024 threads.
// ============================================================
__global__ void __launch_bounds__(1024) mask_kernel()
{
    __shared__ float sx1[TOPK], sy1[TOPK], sx2[TOPK], sy2[TOPK], sar[TOPK];

    const int c = blockIdx.x;
    const int b = blockIdx.y;
    const int t = threadIdx.x;

    {
        int idx = g_topidx[b * TOPK + t];
        float4 bx = g_boxes[(size_t)b * NDET + idx];
        float4 ex = g_extra[(size_t)b * NDET + idx];
        float off = ex.z * CLS_OFF;
        float ax1 = bx.x + off, ay1 = bx.y + off;
        float ax2 = bx.z + off, ay2 = bx.w + off;
        sx1[t] = ax1; sy1[t] = ay1; sx2[t] = ax2; sy2[t] = ay2;
        sar[t] = (ax2 - ax1) * (ay2 - ay1);
    }
    __syncthreads();

    const int row = ((t >> 2) << 2) + c;   // rows == c (mod 4)
    const int wg  = t & 3;                 // words wg*8 .. wg*8+7

    float ax1 = sx1[row], ay1 = sy1[row];
    float ax2 = sx2[row], ay2 = sy2[row];
    float areaA = sar[row];

    unsigned words[8];
    #pragma unroll
    for (int k = 0; k < 8; k++) {
        int w = wg * 8 + k;
        unsigned cur = 0u;
        if ((w + 1) * 32 > row + 1) {
            #pragma unroll 8
            for (int bit = 0; bit < 32; bit++) {
                int j = (w << 5) + bit;
                if (j > row) {
                    float lx = fmaxf(ax1, sx1[j]);
                    float ly = fmaxf(ay1, sy1[j]);
                    float rx = fminf(ax2, sx2[j]);
                    float ry = fminf(ay2, sy2[j]);
                    float ww = fmaxf(rx - lx, 0.0f);
                    float hh = fmaxf(ry - ly, 0.0f);
                    float inter = ww * hh;
                    float iou = inter / (areaA + sar[j] - inter + 1e-9f);
                    if (iou > IOU_T) cur |= (1u << bit);
                }
            }
        }
        words[k] = cur;
    }

    unsigned* gm = &g_mask[((size_t)b * TOPK + row) * 32 + wg * 8];
    ((uint4*)gm)[0] = make_uint4(words[0], words[1], words[2], words[3]);
    ((uint4*)gm)[1] = make_uint4(words[4], words[5], words[6], words[7]);
}

// ============================================================
// Kernel 4: greedy scan + output. 32 blocks x 1024 threads.
// smem: mask copy 128KB + valid words + keep words (dynamic).
// Scan: groups of 32 rows; per-group one shfl, per-bit chain is
// select+or on a preloaded register word (no shfl/LDS in chain).
// ============================================================
#define FINISH_SMEM (TOPK*32*4 + 64*4)

__global__ void __launch_bounds__(1024) finish_kernel(float* __restrict__ out)
{
    extern __shared__ char smemraw[];
    unsigned* smask  = (unsigned*)smemraw;                 // 1024*32 words
    unsigned* vwords = (unsigned*)(smemraw + TOPK * 32 * 4);   // 32
    unsigned* kwords = vwords + 32;                            // 32

    const int b = blockIdx.x;
    const int t = threadIdx.x;
    const int lane = t & 31;
    const int warp = t >> 5;

    // gather candidate row (for valid + output)
    int idx = g_topidx[b * TOPK + t];
    float4 bx = g_boxes[(size_t)b * NDET + idx];
    float4 ex = g_extra[(size_t)b * NDET + idx];

    // valid bits as one word per warp/group
    unsigned vmask = __ballot_sync(0xFFFFFFFFu, ex.x > CNF);
    if (lane == 0) vwords[warp] = vmask;

    // copy mask into smem, coalesced uint4
    {
        const uint4* gm = (const uint4*)&g_mask[(size_t)b * TOPK * 32];
        uint4* sm = (uint4*)smask;
        #pragma unroll
        for (int q = 0; q < 8; q++)
            sm[t + q * 1024] = gm[t + q * 1024];
    }
    __syncthreads();

    // serial greedy scan, warp 0 only. lane owns suppressed word `lane`.
    if (t < 32) {
        unsigned my_sup = 0u;
        #pragma unroll 1
        for (int g = 0; g < 32; g++) {
            const int rbase = g << 5;
            // preload the group's in-group mask words (broadcast loads)
            unsigned mg[32];
            #pragma unroll
            for (int bb = 0; bb < 32; bb++)
                mg[bb] = smask[((rbase + bb) << 5) + g];
            unsigned sg = __shfl_sync(0xFFFFFFFFu, my_sup, g);
            unsigned vw = vwords[g];
            unsigned keepw = 0u;
            #pragma unroll
            for (int bb = 0; bb < 32; bb++) {
                bool kept = (((sg >> bb) & 1u) == 0u) && (((vw >> bb) & 1u) != 0u);
                if (kept) {
                    keepw |= (1u << bb);
                    my_sup |= smask[((rbase + bb) << 5) + lane];  // off-chain
                    sg |= mg[bb];                                 // chain: sel+or
                }
            }
            if (lane == 0) kwords[g] = keepw;
        }
    }
    __syncthreads();

    bool kp = ((kwords[warp] >> lane) & 1u) != 0u;
    float* o = out + ((size_t)b * TOPK + t) * 7;
    if (kp) {
        o[0] = STRIDE_OUT * bx.x; o[1] = STRIDE_OUT * bx.y;
        o[2] = STRIDE_OUT * bx.z; o[3] = STRIDE_OUT * bx.w;
        o[4] = STRIDE_OUT * ex.x; o[5] = STRIDE_OUT * ex.y;
        o[6] = STRIDE_OUT * ex.z;
    } else {
        o[0] = 0.f; o[1] = 0.f; o[2] = 0.f; o[3] = 0.f;
        o[4] = 0.f; o[5] = 0.f; o[6] = 0.f;
    }
    out[(size_t)BATCH * TOPK * 7 + (size_t)b * TOPK + t] = kp ? 1.0f : 0.0f;
}

// ============================================================
extern "C" void kernel_launch(void* const* d_in, const int* in_sizes, int n_in,
                              void* d_out, int out_size)
{
    const float* in = (const float*)d_in[0];
    float* out = (float*)d_out;

    decode_kernel<<<dim3(16, BATCH), dim3(64, 4)>>>(in);
    select_kernel<<<BATCH, 1024>>>();
    mask_kernel<<<dim3(4, BATCH), 1024>>>();

    cudaFuncSetAttribute(finish_kernel, cudaFuncAttributeMaxDynamicSharedMemorySize,
                         FINISH_SMEM);
    finish_kernel<<<BATCH, 1024, FINISH_SMEM>>>(out);
}